// round 4
// baseline (speedup 1.0000x reference)
#include <cuda_runtime.h>
#include <math.h>

// x: (B=4, S=128, H=128, W=128) fp32 ; ada_mask: (B, S, K=21) fp32
// out[b,s,h,w] = sum_k softmax(ada_mask[b,s,:])[k] * xpad[b, s+k-10, h, w]
#define B_DIM    4
#define S_DIM    128
#define HW4_DIM  4096                  // H*W / 4  (float4 pixels per plane)
#define K_DIM    21
#define KP       22                    // K padded to even (weight 21 is zero)
#define PAD      10
#define TILE_S   32                    // output rows (s) per thread
#define THREADS  128
#define WROW     44                    // duplicated weight row: 22 pairs (w,w)
#define WIN      (TILE_S + KP - 1)     // 53 input planes per tile

typedef unsigned long long u64;

// Packed 2-wide fp32 FMA / ADD (Blackwell f32x2 pipe) — one instr, two lanes.
__device__ __forceinline__ u64 fma2(u64 a, u64 b, u64 c) {
    u64 d;
    asm("fma.rn.f32x2 %0, %1, %2, %3;" : "=l"(d) : "l"(a), "l"(b), "l"(c));
    return d;
}
__device__ __forceinline__ u64 add2(u64 a, u64 b) {
    u64 d;
    asm("add.rn.f32x2 %0, %1, %2;" : "=l"(d) : "l"(a), "l"(b));
    return d;
}

__global__ __launch_bounds__(THREADS, 3)
void AdaptiveMixing_28784870818046_kernel(const ulonglong2* __restrict__ x,
                                          const float*      __restrict__ ada_mask,
                                          ulonglong2*       __restrict__ out)
{
    // duplicated softmax weights: row j holds 22 pairs (w_k, w_k), k=21 is zero
    __shared__ __align__(16) float ws[TILE_S * WROW];

    const int b  = blockIdx.z;
    const int s0 = blockIdx.y * TILE_S;
    const int p  = blockIdx.x * THREADS + threadIdx.x;   // float4-pixel idx [0, HW4)

    // ---- per-(b,s) softmax over K=21, stored duplicated: ws[j][2k]=ws[j][2k+1]=w_k ----
    if (threadIdx.x < TILE_S) {
        const int s = s0 + threadIdx.x;
        const float* m = ada_mask + ((size_t)b * S_DIM + s) * K_DIM;
        float mv[K_DIM];
        float mx = -3.402823466e+38f;
        #pragma unroll
        for (int k = 0; k < K_DIM; ++k) { mv[k] = m[k]; mx = fmaxf(mx, mv[k]); }
        float sum = 0.f;
        #pragma unroll
        for (int k = 0; k < K_DIM; ++k) { mv[k] = expf(mv[k] - mx); sum += mv[k]; }
        const float inv = 1.0f / sum;
        float* row = ws + threadIdx.x * WROW;
        #pragma unroll
        for (int k = 0; k < K_DIM; ++k) {
            const float w = mv[k] * inv;
            row[2 * k]     = w;
            row[2 * k + 1] = w;
        }
        row[42] = 0.f;   // zero pair for k=21
        row[43] = 0.f;
    }
    __syncthreads();

    const ulonglong2* xb = x + (size_t)b * S_DIM * HW4_DIM + p;
    ulonglong2*       ob = out + ((size_t)b * S_DIM + s0) * HW4_DIM + p;

    // ---- rolling 22-plane float4 window over a fully unrolled 32-row loop ----
    ulonglong2 win[WIN];
    const ulonglong2 z2 = make_ulonglong2(0ULL, 0ULL);

    // preload planes 0..20  (plane i holds x[s0-10+i]; out of range -> 0)
    #pragma unroll
    for (int i = 0; i < KP - 1; ++i) {
        const int s = s0 - PAD + i;
        win[i] = (s >= 0 && s < S_DIM) ? xb[(size_t)s * HW4_DIM] : z2;
    }

    #pragma unroll
    for (int j = 0; j < TILE_S; ++j) {
        // fetch plane j+21 (consumed only by k=21's zero weight this row,
        // real use starts at row j+1) -> 21-row prefetch distance
        {
            const int s = s0 - PAD + j + KP - 1;     // s = s0 + j + 11  (>= 11, only top clip)
            win[j + KP - 1] = (s < S_DIM) ? xb[(size_t)s * HW4_DIM] : z2;
        }

        const ulonglong2* wr = reinterpret_cast<const ulonglong2*>(ws + j * WROW);
        u64 a0 = 0ULL, a1 = 0ULL, b0 = 0ULL, b1 = 0ULL;   // 2 chains x 2 pixel-pairs
        #pragma unroll
        for (int q = 0; q < 11; ++q) {
            const ulonglong2 wp = wr[q];          // .x=(w2q,w2q) .y=(w2q+1,w2q+1)
            const ulonglong2 v0 = win[j + 2 * q];
            const ulonglong2 v1 = win[j + 2 * q + 1];
            a0 = fma2(wp.x, v0.x, a0);
            a1 = fma2(wp.x, v0.y, a1);
            b0 = fma2(wp.y, v1.x, b0);
            b1 = fma2(wp.y, v1.y, b1);
        }
        ulonglong2 r;
        r.x = add2(a0, b0);
        r.y = add2(a1, b1);
        ob[(size_t)j * HW4_DIM] = r;
    }
}

extern "C" void kernel_launch(void* const* d_in, const int* in_sizes, int n_in,
                              void* d_out, int out_size)
{
    const ulonglong2* x   = (const ulonglong2*)d_in[0];  // (4,128,128,128) fp32 as float4
    const float* ada_mask = (const float*)d_in[1];       // (4,128,21) fp32
    ulonglong2* out       = (ulonglong2*)d_out;

    dim3 grid(HW4_DIM / THREADS,   // 32 pixel-blocks
              S_DIM / TILE_S,      // 4 s-tiles
              B_DIM);              // 4 batches
    AdaptiveMixing_28784870818046_kernel<<<grid, THREADS>>>(x, ada_mask, out);
}

// round 5
// speedup vs baseline: 1.0587x; 1.0587x over previous
#include <cuda_runtime.h>
#include <math.h>

// x: (B=4, S=128, H=128, W=128) fp32 ; ada_mask: (B, S, K=21) fp32
// out[b,s,h,w] = sum_k softmax(ada_mask[b,s,:])[k] * xpad[b, s+k-10, h, w]
#define B_DIM    4
#define S_DIM    128
#define HW4_DIM  4096                  // H*W / 4  (float4 pixels per plane)
#define K_DIM    21
#define KP       22                    // K padded to even (weight 21 is zero)
#define PAD      10
#define TILE_S   16                    // output rows (s) per thread
#define THREADS  128
#define WROW     44                    // duplicated weight row: 22 pairs (w,w)
#define WIN      (TILE_S + KP - 1)     // 37 input planes touched per tile

typedef unsigned long long u64;

// Packed 2-wide fp32 FMA / ADD (Blackwell f32x2) — one instr, two fp32 lanes.
__device__ __forceinline__ u64 fma2(u64 a, u64 b, u64 c) {
    u64 d;
    asm("fma.rn.f32x2 %0, %1, %2, %3;" : "=l"(d) : "l"(a), "l"(b), "l"(c));
    return d;
}
__device__ __forceinline__ u64 add2(u64 a, u64 b) {
    u64 d;
    asm("add.rn.f32x2 %0, %1, %2;" : "=l"(d) : "l"(a), "l"(b));
    return d;
}

__global__ __launch_bounds__(THREADS, 4)
void AdaptiveMixing_28784870818046_kernel(const ulonglong2* __restrict__ x,
                                          const float*      __restrict__ ada_mask,
                                          ulonglong2*       __restrict__ out)
{
    // duplicated softmax weights: row j holds 22 pairs (w_k, w_k); k=21 pair is zero
    __shared__ __align__(16) float ws[TILE_S * WROW];

    const int b  = blockIdx.z;
    const int s0 = blockIdx.y * TILE_S;
    const int p  = blockIdx.x * THREADS + threadIdx.x;   // float4-pixel idx [0, HW4)

    // ---- per-(b,s) softmax over K=21, stored duplicated ----
    if (threadIdx.x < TILE_S) {
        const int s = s0 + threadIdx.x;
        const float* m = ada_mask + ((size_t)b * S_DIM + s) * K_DIM;
        float mv[K_DIM];
        float mx = -3.402823466e+38f;
        #pragma unroll
        for (int k = 0; k < K_DIM; ++k) { mv[k] = m[k]; mx = fmaxf(mx, mv[k]); }
        float sum = 0.f;
        #pragma unroll
        for (int k = 0; k < K_DIM; ++k) { mv[k] = expf(mv[k] - mx); sum += mv[k]; }
        const float inv = 1.0f / sum;
        float* row = ws + threadIdx.x * WROW;
        #pragma unroll
        for (int k = 0; k < K_DIM; ++k) {
            const float w = mv[k] * inv;
            row[2 * k]     = w;
            row[2 * k + 1] = w;
        }
        row[42] = 0.f;   // zero pair for k=21
        row[43] = 0.f;
    }
    __syncthreads();

    const ulonglong2* xb = x + (size_t)b * S_DIM * HW4_DIM + p;
    ulonglong2*       ob = out + ((size_t)b * S_DIM + s0) * HW4_DIM + p;

    // ---- rolling 22-plane float4 window over a fully unrolled 16-row loop ----
    ulonglong2 win[WIN];
    const ulonglong2 z2 = make_ulonglong2(0ULL, 0ULL);

    // preload planes 0..20  (plane i holds x[s0-10+i]; out of range -> 0)
    #pragma unroll
    for (int i = 0; i < KP - 1; ++i) {
        const int s = s0 - PAD + i;
        win[i] = (s >= 0 && s < S_DIM) ? xb[(size_t)s * HW4_DIM] : z2;
    }

    #pragma unroll
    for (int j = 0; j < TILE_S; ++j) {
        // fetch plane j+21 (pairs with the zero k=21 weight this row; real use
        // starts next row) -> full-row prefetch distance
        {
            const int s = s0 - PAD + j + KP - 1;     // s = s0 + j + 11 (only top clip)
            win[j + KP - 1] = (s < S_DIM) ? xb[(size_t)s * HW4_DIM] : z2;
        }

        const ulonglong2* wr = reinterpret_cast<const ulonglong2*>(ws + j * WROW);
        u64 a0 = 0ULL, a1 = 0ULL, b0 = 0ULL, b1 = 0ULL;   // 2 chains x 2 pixel-pairs
        #pragma unroll
        for (int q = 0; q < 11; ++q) {
            const ulonglong2 wp = wr[q];          // .x=(w2q,w2q) .y=(w2q+1,w2q+1)
            const ulonglong2 v0 = win[j + 2 * q];
            const ulonglong2 v1 = win[j + 2 * q + 1];
            a0 = fma2(wp.x, v0.x, a0);
            a1 = fma2(wp.x, v0.y, a1);
            b0 = fma2(wp.y, v1.x, b0);
            b1 = fma2(wp.y, v1.y, b1);
        }
        ulonglong2 r;
        r.x = add2(a0, b0);
        r.y = add2(a1, b1);
        ob[(size_t)j * HW4_DIM] = r;
    }
}

extern "C" void kernel_launch(void* const* d_in, const int* in_sizes, int n_in,
                              void* d_out, int out_size)
{
    const ulonglong2* x   = (const ulonglong2*)d_in[0];  // (4,128,128,128) fp32 as float4
    const float* ada_mask = (const float*)d_in[1];       // (4,128,21) fp32
    ulonglong2* out       = (ulonglong2*)d_out;

    dim3 grid(HW4_DIM / THREADS,   // 32 pixel-blocks
              S_DIM / TILE_S,      // 8 s-tiles
              B_DIM);              // 4 batches
    AdaptiveMixing_28784870818046_kernel<<<grid, THREADS>>>(x, ada_mask, out);
}